// round 3
// baseline (speedup 1.0000x reference)
#include <cuda_runtime.h>
#include <cuda_bf16.h>
#include <cstdint>

// Problem constants (from reference):
//   R_MAX=32, S_MAX=2 -> C_R = 66, C_S = 6, DIM_PAIR = 128
//   W rows: [0,66) = W_si, [66,132) = W_ti, 132 = w_ent, [133,139) = W_sym
#define DIM    128
#define NCTA   296    // 2 CTAs/SM
#define CHUNK  16     // j's per work chunk (one fixed i per chunk)

__global__ __launch_bounds__(1024, 2)
void rpe_kernel(const int* __restrict__ seq_index,
                const int* __restrict__ seq_color,
                const int* __restrict__ seq_sym,
                const int* __restrict__ seq_entity,
                const int* __restrict__ token_index,
                const float* __restrict__ W,
                float* __restrict__ out,
                int L)
{
    // Tables (folded):
    //   sT1[d]  = W_si[d] + W_ti[65]                (66 rows) — d_ti==65 fast path folded
    //   sSym[d] = W_sym[d] + (d!=5)*w_ent           (6 rows)  — bij_entity <=> d_sym!=5
    //   skey[j] = color | entity<<2 | sym<<4 | seq_index<<6 | token_index<<16
    __shared__ float    sT1[66 * DIM];
    __shared__ float    sSym[6 * DIM];
    __shared__ unsigned skey[1024];

    const int tid = threadIdx.x;

    for (int idx = tid; idx < 66 * DIM; idx += blockDim.x) {
        int k = idx & (DIM - 1);
        sT1[idx] = W[idx] + W[131 * DIM + k];
    }
    for (int idx = tid; idx < 6 * DIM; idx += blockDim.x) {
        int d = idx >> 7, k = idx & (DIM - 1);
        float v = W[(133 + d) * DIM + k];
        if (d != 5) v += W[132 * DIM + k];
        sSym[idx] = v;
    }
    for (int j = tid; j < L; j += blockDim.x) {
        unsigned c  = (unsigned)__ldg(seq_color  + j) & 3u;
        unsigned e  = (unsigned)__ldg(seq_entity + j) & 3u;
        unsigned s  = (unsigned)__ldg(seq_sym    + j) & 3u;
        unsigned si = (unsigned)__ldg(seq_index  + j) & 0x3FFu;
        unsigned ti = (unsigned)__ldg(token_index + j) & 0x3FFu;
        skey[j] = c | (e << 2) | (s << 4) | (si << 6) | (ti << 16);
    }
    __syncthreads();

    const int lane = tid & 31;
    const int warp = tid >> 5;

    // i-independent hot rows in registers:
    const float4 base = *reinterpret_cast<const float4*>(sT1  + 65 * DIM + lane * 4);
    const float4 sym5 = *reinterpret_cast<const float4*>(sSym + 5 * DIM  + lane * 4);
    const float4 hot  = make_float4(base.x + sym5.x, base.y + sym5.y,
                                    base.z + sym5.z, base.w + sym5.w);

    const int chunks_per_row = L / CHUNK;                 // 64 for L=1024
    const int nchunks        = L * chunks_per_row;        // 65536
    const int total_warps    = gridDim.x * (blockDim.x >> 5);
    const int gwarp          = blockIdx.x * (blockDim.x >> 5) + warp;

    float4* __restrict__ out4 = reinterpret_cast<float4*>(out);

    for (int c = gwarp; c < nchunks; c += total_warps) {
        const int i  = c / chunks_per_row;                // few divides per warp total
        const int j0 = (c - i * chunks_per_row) * CHUNK;

        const unsigned ki   = skey[i];
        const int      si_i = (int)((ki >> 6)  & 0x3FFu);
        const int      ti_i = (int)((ki >> 16) & 0x3FFu);
        const int      ss_i = (int)((ki >> 4)  & 3u);

        float4* __restrict__ dst = out4 + ((size_t)i * L + j0) * (DIM / 4) + lane;

        #pragma unroll 4
        for (int jj = 0; jj < CHUNK; jj++) {
            const unsigned kj = skey[j0 + jj];
            const unsigned x  = ki ^ kj;

            float4 v;
            if ((x & 3u) && (x & 12u)) {
                v = hot;                                  // ~56%: no table reads
            } else {
                if (!(x & 3u)) {                          // same color
                    const int sij = (int)((kj >> 6) & 0x3FFu);
                    int d = min(max(si_i - sij, -32), 32) + 32;
                    v = *reinterpret_cast<const float4*>(sT1 + d * DIM + lane * 4);
                    if (si_i == sij) {                    // very rare: real token bin
                        const int tij = (int)((kj >> 16) & 0x3FFu);
                        int dt = min(max(ti_i - tij, -32), 32) + 32;
                        float4 wt  = __ldg(reinterpret_cast<const float4*>(W + (66 + dt) * DIM + lane * 4));
                        float4 w65 = __ldg(reinterpret_cast<const float4*>(W + 131 * DIM       + lane * 4));
                        v.x += wt.x - w65.x; v.y += wt.y - w65.y;
                        v.z += wt.z - w65.z; v.w += wt.w - w65.w;
                    }
                } else {
                    v = base;
                }
                float4 s;
                if (!(x & 12u)) {                         // same entity
                    const int ssj = (int)((kj >> 4) & 3u);
                    int ds = min(max(ss_i - ssj, -2), 2) + 2;
                    s = *reinterpret_cast<const float4*>(sSym + ds * DIM + lane * 4);
                } else {
                    s = sym5;
                }
                v.x += s.x; v.y += s.y; v.z += s.z; v.w += s.w;
            }

            __stcs(dst, v);                               // streaming: write-once output
            dst += DIM / 4;
        }
    }
}

extern "C" void kernel_launch(void* const* d_in, const int* in_sizes, int n_in,
                              void* d_out, int out_size)
{
    const int* seq_index   = (const int*)d_in[0];
    const int* seq_color   = (const int*)d_in[1];
    const int* seq_sym     = (const int*)d_in[2];
    const int* seq_entity  = (const int*)d_in[3];
    const int* token_index = (const int*)d_in[4];
    const float* W         = (const float*)d_in[5];
    float* out             = (float*)d_out;

    const int L = in_sizes[0];   // 1024 (B=1)

    rpe_kernel<<<NCTA, 1024>>>(seq_index, seq_color, seq_sym, seq_entity,
                               token_index, W, out, L);
}

// round 4
// speedup vs baseline: 1.0225x; 1.0225x over previous
#include <cuda_runtime.h>
#include <cuda_bf16.h>
#include <cstdint>

// Problem constants (from reference):
//   R_MAX=32, S_MAX=2 -> C_R = 66, C_S = 6, DIM_PAIR = 128
//   W rows: [0,66) = W_si, [66,132) = W_ti, 132 = w_ent, [133,139) = W_sym
#define DIM   128
#define NCTA  304    // 2 CTAs/SM on 152-SM GB300

__global__ __launch_bounds__(1024, 2)
void rpe_kernel(const int* __restrict__ seq_index,
                const int* __restrict__ seq_color,
                const int* __restrict__ seq_sym,
                const int* __restrict__ seq_entity,
                const int* __restrict__ token_index,
                const float* __restrict__ W,
                float* __restrict__ out,
                int L)
{
    // Tables (folded):
    //   sT1[d]  = W_si[d] + W_ti[65]      (66 rows) — d_ti==65 fast path folded in
    //   sSym[d] = W_sym[d] + (d!=5)*w_ent (6 rows)  — bij_entity <=> d_sym!=5
    //   skey[j] = color | entity<<2 | sym<<4 | seq_index<<6 | token_index<<16
    __shared__ float    sT1[66 * DIM];
    __shared__ float    sSym[6 * DIM];
    __shared__ unsigned skey[1024];

    const int tid = threadIdx.x;

    for (int idx = tid; idx < 66 * DIM; idx += blockDim.x) {
        int k = idx & (DIM - 1);
        sT1[idx] = W[idx] + W[131 * DIM + k];
    }
    for (int idx = tid; idx < 6 * DIM; idx += blockDim.x) {
        int d = idx >> 7, k = idx & (DIM - 1);
        float v = W[(133 + d) * DIM + k];
        if (d != 5) v += W[132 * DIM + k];
        sSym[idx] = v;
    }
    for (int j = tid; j < L; j += blockDim.x) {
        unsigned c  = (unsigned)__ldg(seq_color  + j) & 3u;
        unsigned e  = (unsigned)__ldg(seq_entity + j) & 3u;
        unsigned s  = (unsigned)__ldg(seq_sym    + j) & 3u;
        unsigned si = (unsigned)__ldg(seq_index  + j) & 0x3FFu;
        unsigned ti = (unsigned)__ldg(token_index + j) & 0x3FFu;
        skey[j] = c | (e << 2) | (s << 4) | (si << 6) | (ti << 16);
    }
    __syncthreads();

    const int lane = tid & 31;
    const int warp = tid >> 5;

    // i-independent hot rows in registers:
    const float4 base = *reinterpret_cast<const float4*>(sT1  + 65 * DIM + lane * 4);
    const float4 sym5 = *reinterpret_cast<const float4*>(sSym + 5 * DIM  + lane * 4);
    const float4 hot  = make_float4(base.x + sym5.x, base.y + sym5.y,
                                    base.z + sym5.z, base.w + sym5.w);

    // One pair per warp per step, consecutive warps on consecutive pairs:
    // keeps the chip-wide instantaneous write window contiguous (~5MB), which
    // R2 vs R3 showed is worth real DRAM-write efficiency.
    const long long npairs      = (long long)L * (long long)L;
    const int       total_warps = gridDim.x * (blockDim.x >> 5);
    const int       gwarp       = blockIdx.x * (blockDim.x >> 5) + warp;

    // Incremental (i, j) bookkeeping — no per-step div/mod.
    const int step_i = total_warps / L;
    const int step_j = total_warps - step_i * L;

    long long p = gwarp;
    int i = (int)(p / L);
    int j = (int)(p - (long long)i * L);

    float4* __restrict__ dst =
        reinterpret_cast<float4*>(out) + p * (DIM / 4) + lane;
    const long long dst_step = (long long)total_warps * (DIM / 4);

    while (p < npairs) {
        const unsigned ki = skey[i];
        const unsigned kj = skey[j];
        const unsigned x  = ki ^ kj;

        float4 v;
        if ((x & 3u) && (x & 12u)) {
            v = hot;                                    // ~56%: no table reads
        } else {
            if (!(x & 3u)) {                            // same color
                const int si_i = (int)((ki >> 6) & 0x3FFu);
                const int sij  = (int)((kj >> 6) & 0x3FFu);
                int d = min(max(si_i - sij, -32), 32) + 32;
                v = *reinterpret_cast<const float4*>(sT1 + d * DIM + lane * 4);
                if (si_i == sij) {                      // very rare: real token bin
                    const int ti_i = (int)((ki >> 16) & 0x3FFu);
                    const int tij  = (int)((kj >> 16) & 0x3FFu);
                    int dt = min(max(ti_i - tij, -32), 32) + 32;
                    float4 wt  = __ldg(reinterpret_cast<const float4*>(W + (66 + dt) * DIM + lane * 4));
                    float4 w65 = __ldg(reinterpret_cast<const float4*>(W + 131 * DIM       + lane * 4));
                    v.x += wt.x - w65.x; v.y += wt.y - w65.y;
                    v.z += wt.z - w65.z; v.w += wt.w - w65.w;
                }
            } else {
                v = base;
            }
            float4 s;
            if (!(x & 12u)) {                           // same entity
                const int ss_i = (int)((ki >> 4) & 3u);
                const int ssj  = (int)((kj >> 4) & 3u);
                int ds = min(max(ss_i - ssj, -2), 2) + 2;
                s = *reinterpret_cast<const float4*>(sSym + ds * DIM + lane * 4);
            } else {
                s = sym5;
            }
            v.x += s.x; v.y += s.y; v.z += s.z; v.w += s.w;
        }

        __stcs(dst, v);                                 // streaming: write-once output

        // advance one grid-stride step (no div/mod)
        p   += total_warps;
        dst += dst_step;
        i   += step_i;
        j   += step_j;
        if (j >= L) { j -= L; i += 1; }
    }
}

extern "C" void kernel_launch(void* const* d_in, const int* in_sizes, int n_in,
                              void* d_out, int out_size)
{
    const int* seq_index   = (const int*)d_in[0];
    const int* seq_color   = (const int*)d_in[1];
    const int* seq_sym     = (const int*)d_in[2];
    const int* seq_entity  = (const int*)d_in[3];
    const int* token_index = (const int*)d_in[4];
    const float* W         = (const float*)d_in[5];
    float* out             = (float*)d_out;

    const int L = in_sizes[0];   // 1024 (B=1)

    rpe_kernel<<<NCTA, 1024>>>(seq_index, seq_color, seq_sym, seq_entity,
                               token_index, W, out, L);
}

// round 5
// speedup vs baseline: 1.0379x; 1.0151x over previous
#include <cuda_runtime.h>
#include <cuda_bf16.h>
#include <cstdint>

// Problem constants (from reference):
//   R_MAX=32, S_MAX=2 -> C_R = 66, C_S = 6, DIM_PAIR = 128
//   W rows: [0,66) = W_si, [66,132) = W_ti, 132 = w_ent, [133,139) = W_sym
#define DIM   128
#define NCTA  304    // 2 CTAs/SM on 152-SM GB300

__global__ __launch_bounds__(1024, 2)
void rpe_kernel(const int* __restrict__ seq_index,
                const int* __restrict__ seq_color,
                const int* __restrict__ seq_sym,
                const int* __restrict__ seq_entity,
                const int* __restrict__ token_index,
                const float* __restrict__ W,
                float* __restrict__ out,
                int L)
{
    // Tables (folded):
    //   sT1[d]  = W_si[d] + W_ti[65]      (66 rows) — d_ti==65 fast path folded in
    //   sSym[d] = W_sym[d] + (d!=5)*w_ent (6 rows)  — bij_entity <=> d_sym!=5
    //   skey[j] = color | entity<<2 | sym<<4 | seq_index<<6 | token_index<<16
    __shared__ float    sT1[66 * DIM];
    __shared__ float    sSym[6 * DIM];
    __shared__ unsigned skey[1024];

    const int tid = threadIdx.x;

    for (int idx = tid; idx < 66 * DIM; idx += blockDim.x) {
        int k = idx & (DIM - 1);
        sT1[idx] = W[idx] + W[131 * DIM + k];
    }
    for (int idx = tid; idx < 6 * DIM; idx += blockDim.x) {
        int d = idx >> 7, k = idx & (DIM - 1);
        float v = W[(133 + d) * DIM + k];
        if (d != 5) v += W[132 * DIM + k];
        sSym[idx] = v;
    }
    for (int j = tid; j < L; j += blockDim.x) {
        unsigned c  = (unsigned)__ldg(seq_color  + j) & 3u;
        unsigned e  = (unsigned)__ldg(seq_entity + j) & 3u;
        unsigned s  = (unsigned)__ldg(seq_sym    + j) & 3u;
        unsigned si = (unsigned)__ldg(seq_index  + j) & 0x3FFu;
        unsigned ti = (unsigned)__ldg(token_index + j) & 0x3FFu;
        skey[j] = c | (e << 2) | (s << 4) | (si << 6) | (ti << 16);
    }
    __syncthreads();

    const int lane = tid & 31;
    const int warp = tid >> 5;

    // i-independent hot rows in registers:
    const float4 base = *reinterpret_cast<const float4*>(sT1  + 65 * DIM + lane * 4);
    const float4 sym5 = *reinterpret_cast<const float4*>(sSym + 5 * DIM  + lane * 4);
    const float4 hot  = make_float4(base.x + sym5.x, base.y + sym5.y,
                                    base.z + sym5.z, base.w + sym5.w);

    // One pair per warp per step, consecutive warps on consecutive pairs:
    // keeps the chip-wide instantaneous write window contiguous (best DRAM
    // write efficiency per R2 vs R3 evidence). ALL index math is 32-bit.
    const int npairs      = L * L;                       // 2^20: fits int
    const int total_warps = gridDim.x * (blockDim.x >> 5);
    const int gwarp       = blockIdx.x * (blockDim.x >> 5) + warp;

    const int step_i = total_warps / L;                  // 9  (for 9728/1024)
    const int step_j = total_warps - step_i * L;         // 512

    int p = gwarp;
    int i = p / L;                                       // once
    int j = p - i * L;

    float4* __restrict__ dst =
        reinterpret_cast<float4*>(out) + (size_t)p * (DIM / 4) + lane;
    const int dst_step = total_warps * (DIM / 4);        // pointer add only 64-bit op

    #pragma unroll 2
    while (p < npairs) {
        const unsigned ki = skey[i];
        const unsigned kj = skey[j];
        const unsigned x  = ki ^ kj;

        float4 v;
        if ((x & 3u) && (x & 12u)) {
            v = hot;                                     // ~56%: no table reads
        } else {
            if (!(x & 3u)) {                             // same color
                const int si_i = (int)((ki >> 6) & 0x3FFu);
                const int sij  = (int)((kj >> 6) & 0x3FFu);
                int d = min(max(si_i - sij, -32), 32) + 32;
                v = *reinterpret_cast<const float4*>(sT1 + d * DIM + lane * 4);
                if (si_i == sij) {                       // very rare: real token bin
                    const int ti_i = (int)((ki >> 16) & 0x3FFu);
                    const int tij  = (int)((kj >> 16) & 0x3FFu);
                    int dt = min(max(ti_i - tij, -32), 32) + 32;
                    float4 wt  = __ldg(reinterpret_cast<const float4*>(W + (66 + dt) * DIM + lane * 4));
                    float4 w65 = __ldg(reinterpret_cast<const float4*>(W + 131 * DIM       + lane * 4));
                    v.x += wt.x - w65.x; v.y += wt.y - w65.y;
                    v.z += wt.z - w65.z; v.w += wt.w - w65.w;
                }
            } else {
                v = base;
            }
            float4 s;
            if (!(x & 12u)) {                            // same entity
                const int ss_i = (int)((ki >> 4) & 3u);
                const int ssj  = (int)((kj >> 4) & 3u);
                int ds = min(max(ss_i - ssj, -2), 2) + 2;
                s = *reinterpret_cast<const float4*>(sSym + ds * DIM + lane * 4);
            } else {
                s = sym5;
            }
            v.x += s.x; v.y += s.y; v.z += s.z; v.w += s.w;
        }

        __stcs(dst, v);                                  // streaming: write-once output

        // advance one grid-stride step — branch-free 32-bit index update
        p   += total_warps;
        dst += dst_step;
        j   += step_j;
        int wrap = (j >= L);
        i   += step_i + wrap;
        j   -= wrap ? L : 0;
    }
}

extern "C" void kernel_launch(void* const* d_in, const int* in_sizes, int n_in,
                              void* d_out, int out_size)
{
    const int* seq_index   = (const int*)d_in[0];
    const int* seq_color   = (const int*)d_in[1];
    const int* seq_sym     = (const int*)d_in[2];
    const int* seq_entity  = (const int*)d_in[3];
    const int* token_index = (const int*)d_in[4];
    const float* W         = (const float*)d_in[5];
    float* out             = (float*)d_out;

    const int L = in_sizes[0];   // 1024 (B=1)

    rpe_kernel<<<NCTA, 1024>>>(seq_index, seq_color, seq_sym, seq_entity,
                               token_index, W, out, L);
}